// round 3
// baseline (speedup 1.0000x reference)
#include <cuda_runtime.h>
#include <math.h>

#define S_LEN 4096
#define D_MODEL 768
#define N_HEADS 12
#define D_HEAD 64

// ---------------- scratch (no allocations allowed) ----------------
__device__ float g_Q[S_LEN * D_MODEL];
__device__ float g_K[S_LEN * D_MODEL];
__device__ float g_V[S_LEN * D_MODEL];
__device__ float g_CTX[S_LEN * D_MODEL];

// ---------------- tf32 helpers ----------------
__device__ __forceinline__ unsigned cvt_tf32(float f) {
    unsigned r;
    asm("cvt.rna.tf32.f32 %0, %1;" : "=r"(r) : "f"(f));
    return r;
}
__device__ __forceinline__ float cvt_tf32f(float f) {
    return __uint_as_float(cvt_tf32(f));
}
__device__ __forceinline__ void mma_tf32(float* c, const unsigned* a, unsigned b0, unsigned b1) {
    asm volatile(
        "mma.sync.aligned.m16n8k8.row.col.f32.tf32.tf32.f32 "
        "{%0,%1,%2,%3}, {%4,%5,%6,%7}, {%8,%9}, {%0,%1,%2,%3};\n"
        : "+f"(c[0]), "+f"(c[1]), "+f"(c[2]), "+f"(c[3])
        : "r"(a[0]), "r"(a[1]), "r"(a[2]), "r"(a[3]), "r"(b0), "r"(b1));
}

// pair-interleave position of column c within its 8-wide k-group:
// col lc (0..3) -> 2*lc, col lc+4 -> 2*lc+1  => pos = 2*(c&3) + ((c&7)>>2)
__device__ __forceinline__ int pairpos(int c8) { return 2 * (c8 & 3) + (c8 >> 2); }

// ============================================================================
// GEMM (tf32): C[M,N] = (A[M,K] @ B[N,K]^T + bias[N]) * scale
// 128 threads / 4 warps. BM=128 (warp M=32), BN=64, BK=32.
// A and B staged in pair-interleaved layout so fragments load as float2.
// ============================================================================
#define GBM 128
#define GBN 64
#define GBK 32
#define GAS 40   // Ap row stride (32 data + pad)
#define GBS 40   // Bp row stride

__global__ __launch_bounds__(128)
void gemm_tf32(const float* __restrict__ A, const float* __restrict__ B,
               const float* __restrict__ bias, float* __restrict__ C,
               int M, int N, int K, float scale) {
    __shared__ float Ap[GBM * GAS];
    __shared__ float Bp[GBN * GBS];

    const int tid  = threadIdx.x;
    const int warp = tid >> 5;
    const int lane = tid & 31;
    const int lr = lane >> 2;   // 0..7
    const int lc = lane & 3;    // 0..3

    const int crow = blockIdx.y * GBM;
    const int ccol = blockIdx.x * GBN;

    float acc[2][8][4];
    #pragma unroll
    for (int mf = 0; mf < 2; mf++)
        #pragma unroll
        for (int nc = 0; nc < 8; nc++)
            #pragma unroll
            for (int i = 0; i < 4; i++) acc[mf][nc][i] = 0.f;

    for (int kt = 0; kt < K; kt += GBK) {
        // stage A (128x32) pair-interleaved
        #pragma unroll
        for (int it = 0; it < 8; it++) {
            int t = tid + it * 128;          // 0..1023
            int row = t >> 3;                 // 0..127
            int c4  = (t & 7) * 4;            // 0..28
            float4 a4 = *reinterpret_cast<const float4*>(&A[(size_t)(crow + row) * K + kt + c4]);
            int base = row * GAS + (c4 >> 3) * 8;
            Ap[base + pairpos((c4 + 0) & 7)] = cvt_tf32f(a4.x);
            Ap[base + pairpos((c4 + 1) & 7)] = cvt_tf32f(a4.y);
            Ap[base + pairpos((c4 + 2) & 7)] = cvt_tf32f(a4.z);
            Ap[base + pairpos((c4 + 3) & 7)] = cvt_tf32f(a4.w);
        }
        // stage B (64x32) pair-interleaved
        #pragma unroll
        for (int it = 0; it < 4; it++) {
            int t = tid + it * 128;          // 0..511
            int row = t >> 3;                 // 0..63
            int c4  = (t & 7) * 4;
            float4 b4 = *reinterpret_cast<const float4*>(&B[(size_t)(ccol + row) * K + kt + c4]);
            int base = row * GBS + (c4 >> 3) * 8;
            Bp[base + pairpos((c4 + 0) & 7)] = cvt_tf32f(b4.x);
            Bp[base + pairpos((c4 + 1) & 7)] = cvt_tf32f(b4.y);
            Bp[base + pairpos((c4 + 2) & 7)] = cvt_tf32f(b4.z);
            Bp[base + pairpos((c4 + 3) & 7)] = cvt_tf32f(b4.w);
        }
        __syncthreads();

        #pragma unroll
        for (int kc = 0; kc < GBK / 8; kc++) {
            unsigned a[2][4];
            #pragma unroll
            for (int mf = 0; mf < 2; mf++) {
                int r0 = warp * 32 + mf * 16 + lr;
                float2 p0 = *reinterpret_cast<const float2*>(&Ap[(r0    ) * GAS + kc * 8 + 2 * lc]);
                float2 p1 = *reinterpret_cast<const float2*>(&Ap[(r0 + 8) * GAS + kc * 8 + 2 * lc]);
                a[mf][0] = __float_as_uint(p0.x); a[mf][2] = __float_as_uint(p0.y);
                a[mf][1] = __float_as_uint(p1.x); a[mf][3] = __float_as_uint(p1.y);
            }
            #pragma unroll
            for (int nc = 0; nc < 8; nc++) {
                float2 bp = *reinterpret_cast<const float2*>(&Bp[(nc * 8 + lr) * GBS + kc * 8 + 2 * lc]);
                unsigned b0 = __float_as_uint(bp.x), b1 = __float_as_uint(bp.y);
                mma_tf32(acc[0][nc], a[0], b0, b1);
                mma_tf32(acc[1][nc], a[1], b0, b1);
            }
        }
        __syncthreads();
    }

    // epilogue
    #pragma unroll
    for (int mf = 0; mf < 2; mf++) {
        int row0 = crow + warp * 32 + mf * 16 + lr;
        #pragma unroll
        for (int nc = 0; nc < 8; nc++) {
            int col = ccol + nc * 8 + 2 * lc;
            float b0 = bias[col], b1 = bias[col + 1];
            float2 v0, v1;
            v0.x = (acc[mf][nc][0] + b0) * scale;
            v0.y = (acc[mf][nc][1] + b1) * scale;
            v1.x = (acc[mf][nc][2] + b0) * scale;
            v1.y = (acc[mf][nc][3] + b1) * scale;
            *reinterpret_cast<float2*>(&C[(size_t)row0 * N + col])       = v0;
            *reinterpret_cast<float2*>(&C[(size_t)(row0 + 8) * N + col]) = v1;
        }
    }
}

// ============================================================================
// Flash attention (tf32). 128 threads / 4 warps, warp M=32 -> BQ=128.
// K tile: pair-interleaved [64][72]; V tile: k-paired transposed [8][64][8];
// P: per-warp [32][68].
// ============================================================================
#define FBQ 128
#define FBK 64
#define KS 72
#define PS 68
#define K_FLOATS (64 * KS)            // 4608
#define V_FLOATS (8 * 64 * 8)         // 4096
#define P_FLOATS (4 * 32 * PS)        // 8704
#define FSMEM_FLOATS (K_FLOATS + V_FLOATS + P_FLOATS + 64)

__global__ __launch_bounds__(128)
void flash_attn_mma(const float* __restrict__ Q, const float* __restrict__ K,
                    const float* __restrict__ V, const int* __restrict__ mask,
                    float* __restrict__ Ctx) {
    extern __shared__ float sm[];
    float* Ksh = sm;                    // [64][KS] pair-interleaved along k
    float* Vt  = Ksh + K_FLOATS;        // [(kc*64 + d)*8 + pairpos(key&7)]
    float* Psh = Vt + V_FLOATS;         // per warp [32][PS]
    float* msk = Psh + P_FLOATS;

    const int h  = blockIdx.y;
    const int q0 = blockIdx.x * FBQ;
    const int tid  = threadIdx.x;
    const int warp = tid >> 5;
    const int lane = tid & 31;
    const int lr = lane >> 2;
    const int lc = lane & 3;

    float* Pw = Psh + warp * 32 * PS;

    // Q fragments: 2 m16 fragments (32 rows) held in registers
    unsigned aq[2][8][4];
    #pragma unroll
    for (int mf = 0; mf < 2; mf++) {
        const float* Qb = Q + (size_t)(q0 + warp * 32 + mf * 16) * D_MODEL + h * D_HEAD;
        #pragma unroll
        for (int kc = 0; kc < 8; kc++) {
            aq[mf][kc][0] = cvt_tf32(Qb[(size_t)(lr    ) * D_MODEL + kc * 8 + lc    ]);
            aq[mf][kc][1] = cvt_tf32(Qb[(size_t)(lr + 8) * D_MODEL + kc * 8 + lc    ]);
            aq[mf][kc][2] = cvt_tf32(Qb[(size_t)(lr    ) * D_MODEL + kc * 8 + lc + 4]);
            aq[mf][kc][3] = cvt_tf32(Qb[(size_t)(lr + 8) * D_MODEL + kc * 8 + lc + 4]);
        }
    }

    float o[2][8][4];
    #pragma unroll
    for (int mf = 0; mf < 2; mf++)
        #pragma unroll
        for (int nc = 0; nc < 8; nc++)
            #pragma unroll
            for (int i = 0; i < 4; i++) o[mf][nc][i] = 0.f;
    float mrow[2][2] = {{-1e30f, -1e30f}, {-1e30f, -1e30f}};
    float lrow[2][2] = {{0.f, 0.f}, {0.f, 0.f}};

    for (int kt = 0; kt < S_LEN; kt += FBK) {
        __syncthreads();
        // stage K (pair-interleaved along k) and V (k-paired transposed)
        #pragma unroll
        for (int it = 0; it < 8; it++) {
            int t = tid + it * 128;          // 0..1023
            int row = t >> 4;                 // 0..63
            int c4  = (t & 15) * 4;           // 0..60
            const float* kp = K + (size_t)(kt + row) * D_MODEL + h * D_HEAD + c4;
            const float* vp = V + (size_t)(kt + row) * D_MODEL + h * D_HEAD + c4;
            float4 k4 = *reinterpret_cast<const float4*>(kp);
            float4 v4 = *reinterpret_cast<const float4*>(vp);
            int kb = row * KS + (c4 >> 3) * 8;
            Ksh[kb + pairpos((c4 + 0) & 7)] = cvt_tf32f(k4.x);
            Ksh[kb + pairpos((c4 + 1) & 7)] = cvt_tf32f(k4.y);
            Ksh[kb + pairpos((c4 + 2) & 7)] = cvt_tf32f(k4.z);
            Ksh[kb + pairpos((c4 + 3) & 7)] = cvt_tf32f(k4.w);
            int kc = row >> 3, pp = pairpos(row & 7);
            Vt[(kc * 64 + c4 + 0) * 8 + pp] = cvt_tf32f(v4.x);
            Vt[(kc * 64 + c4 + 1) * 8 + pp] = cvt_tf32f(v4.y);
            Vt[(kc * 64 + c4 + 2) * 8 + pp] = cvt_tf32f(v4.z);
            Vt[(kc * 64 + c4 + 3) * 8 + pp] = cvt_tf32f(v4.w);
        }
        if (tid < FBK) msk[tid] = (mask[kt + tid] != 0) ? 0.f : -1e30f;
        __syncthreads();

        // S = Q @ K^T : each B fragment feeds both m-fragments
        float cs[2][8][4];
        #pragma unroll
        for (int mf = 0; mf < 2; mf++)
            #pragma unroll
            for (int nc = 0; nc < 8; nc++)
                #pragma unroll
                for (int i = 0; i < 4; i++) cs[mf][nc][i] = 0.f;
        #pragma unroll
        for (int kc = 0; kc < 8; kc++) {
            #pragma unroll
            for (int nc = 0; nc < 8; nc++) {
                float2 kb = *reinterpret_cast<const float2*>(&Ksh[(nc * 8 + lr) * KS + kc * 8 + 2 * lc]);
                unsigned b0 = __float_as_uint(kb.x), b1 = __float_as_uint(kb.y);
                mma_tf32(cs[0][nc], aq[0][kc], b0, b1);
                mma_tf32(cs[1][nc], aq[1][kc], b0, b1);
            }
        }

        // mask + online softmax per m-fragment
        #pragma unroll
        for (int mf = 0; mf < 2; mf++) {
            #pragma unroll
            for (int nc = 0; nc < 8; nc++) {
                float mk0 = msk[nc * 8 + 2 * lc];
                float mk1 = msk[nc * 8 + 2 * lc + 1];
                cs[mf][nc][0] += mk0; cs[mf][nc][1] += mk1;
                cs[mf][nc][2] += mk0; cs[mf][nc][3] += mk1;
            }
            float mx0 = -1e30f, mx1 = -1e30f;
            #pragma unroll
            for (int nc = 0; nc < 8; nc++) {
                mx0 = fmaxf(mx0, fmaxf(cs[mf][nc][0], cs[mf][nc][1]));
                mx1 = fmaxf(mx1, fmaxf(cs[mf][nc][2], cs[mf][nc][3]));
            }
            mx0 = fmaxf(mx0, __shfl_xor_sync(0xffffffff, mx0, 1));
            mx0 = fmaxf(mx0, __shfl_xor_sync(0xffffffff, mx0, 2));
            mx1 = fmaxf(mx1, __shfl_xor_sync(0xffffffff, mx1, 1));
            mx1 = fmaxf(mx1, __shfl_xor_sync(0xffffffff, mx1, 2));

            float m0n = fmaxf(mrow[mf][0], mx0);
            float m1n = fmaxf(mrow[mf][1], mx1);
            float corr0 = __expf(mrow[mf][0] - m0n);
            float corr1 = __expf(mrow[mf][1] - m1n);
            mrow[mf][0] = m0n; mrow[mf][1] = m1n;
            lrow[mf][0] *= corr0; lrow[mf][1] *= corr1;
            #pragma unroll
            for (int nc = 0; nc < 8; nc++) {
                o[mf][nc][0] *= corr0; o[mf][nc][1] *= corr0;
                o[mf][nc][2] *= corr1; o[mf][nc][3] *= corr1;
            }
            // P = exp(S - m), write to per-warp smem tile
            #pragma unroll
            for (int nc = 0; nc < 8; nc++) {
                float p0 = __expf(cs[mf][nc][0] - m0n);
                float p1 = __expf(cs[mf][nc][1] - m0n);
                float p2 = __expf(cs[mf][nc][2] - m1n);
                float p3 = __expf(cs[mf][nc][3] - m1n);
                lrow[mf][0] += p0 + p1;
                lrow[mf][1] += p2 + p3;
                float2 w0; w0.x = cvt_tf32f(p0); w0.y = cvt_tf32f(p1);
                float2 w1; w1.x = cvt_tf32f(p2); w1.y = cvt_tf32f(p3);
                *reinterpret_cast<float2*>(&Pw[(mf * 16 + lr    ) * PS + nc * 8 + 2 * lc]) = w0;
                *reinterpret_cast<float2*>(&Pw[(mf * 16 + lr + 8) * PS + nc * 8 + 2 * lc]) = w1;
            }
        }
        __syncwarp();

        // O += P @ V : each V fragment feeds both m-fragments
        #pragma unroll
        for (int kc = 0; kc < 8; kc++) {
            unsigned a[2][4];
            #pragma unroll
            for (int mf = 0; mf < 2; mf++) {
                a[mf][0] = __float_as_uint(Pw[(mf * 16 + lr    ) * PS + kc * 8 + lc    ]);
                a[mf][1] = __float_as_uint(Pw[(mf * 16 + lr + 8) * PS + kc * 8 + lc    ]);
                a[mf][2] = __float_as_uint(Pw[(mf * 16 + lr    ) * PS + kc * 8 + lc + 4]);
                a[mf][3] = __float_as_uint(Pw[(mf * 16 + lr + 8) * PS + kc * 8 + lc + 4]);
            }
            #pragma unroll
            for (int nc = 0; nc < 8; nc++) {
                float2 vb = *reinterpret_cast<const float2*>(&Vt[(kc * 64 + nc * 8 + lr) * 8 + 2 * lc]);
                unsigned b0 = __float_as_uint(vb.x), b1 = __float_as_uint(vb.y);
                mma_tf32(o[0][nc], a[0], b0, b1);
                mma_tf32(o[1][nc], a[1], b0, b1);
            }
        }
    }

    // finalize
    #pragma unroll
    for (int mf = 0; mf < 2; mf++) {
        float l0 = lrow[mf][0], l1 = lrow[mf][1];
        l0 += __shfl_xor_sync(0xffffffff, l0, 1);
        l0 += __shfl_xor_sync(0xffffffff, l0, 2);
        l1 += __shfl_xor_sync(0xffffffff, l1, 1);
        l1 += __shfl_xor_sync(0xffffffff, l1, 2);
        float inv0 = 1.f / l0;
        float inv1 = 1.f / l1;
        float* O0 = Ctx + (size_t)(q0 + warp * 32 + mf * 16 + lr) * D_MODEL + h * D_HEAD;
        float* O1 = O0 + (size_t)8 * D_MODEL;
        #pragma unroll
        for (int nc = 0; nc < 8; nc++) {
            int col = nc * 8 + 2 * lc;
            float2 v0; v0.x = o[mf][nc][0] * inv0; v0.y = o[mf][nc][1] * inv0;
            float2 v1; v1.x = o[mf][nc][2] * inv1; v1.y = o[mf][nc][3] * inv1;
            *reinterpret_cast<float2*>(&O0[col]) = v0;
            *reinterpret_cast<float2*>(&O1[col]) = v1;
        }
    }
}

// ---------------- launch ----------------
extern "C" void kernel_launch(void* const* d_in, const int* in_sizes, int n_in,
                              void* d_out, int out_size) {
    const float* query = (const float*)d_in[0];
    const float* key   = (const float*)d_in[1];
    const float* value = (const float*)d_in[2];
    const int*   mask  = (const int*)d_in[3];
    const float* Wq = (const float*)d_in[4];
    const float* bq = (const float*)d_in[5];
    const float* Wk = (const float*)d_in[6];
    const float* bk = (const float*)d_in[7];
    const float* Wv = (const float*)d_in[8];
    const float* bv = (const float*)d_in[9];
    const float* Wo = (const float*)d_in[10];
    const float* bo = (const float*)d_in[11];
    float* out = (float*)d_out;

    void *pQ, *pK, *pV, *pC;
    cudaGetSymbolAddress(&pQ, g_Q);
    cudaGetSymbolAddress(&pK, g_K);
    cudaGetSymbolAddress(&pV, g_V);
    cudaGetSymbolAddress(&pC, g_CTX);

    static int smem_set = 0;
    const int fsmem = FSMEM_FLOATS * (int)sizeof(float);
    if (!smem_set) {
        cudaFuncSetAttribute(flash_attn_mma, cudaFuncAttributeMaxDynamicSharedMemorySize, fsmem);
        smem_set = 1;
    }

    dim3 gridP(D_MODEL / GBN, S_LEN / GBM);   // (12, 32)
    const float qscale = 1.0f / 8.0f;         // 1/sqrt(64)

    gemm_tf32<<<gridP, 128>>>(query, Wq, bq, (float*)pQ, S_LEN, D_MODEL, D_MODEL, qscale);
    gemm_tf32<<<gridP, 128>>>(key,   Wk, bk, (float*)pK, S_LEN, D_MODEL, D_MODEL, 1.0f);
    gemm_tf32<<<gridP, 128>>>(value, Wv, bv, (float*)pV, S_LEN, D_MODEL, D_MODEL, 1.0f);

    dim3 gridA(S_LEN / FBQ, N_HEADS);         // (32, 12)
    flash_attn_mma<<<gridA, 128, fsmem>>>((const float*)pQ, (const float*)pK,
                                          (const float*)pV, mask, (float*)pC);

    gemm_tf32<<<gridP, 128>>>((const float*)pC, Wo, bo, out, S_LEN, D_MODEL, D_MODEL, 1.0f);
}